// round 10
// baseline (speedup 1.0000x reference)
#include <cuda_runtime.h>
#include <cuda_bf16.h>
#include <math.h>

#define H 512
#define W 512
#define B 32
#define CELL 16
#define NC 32            // cells per dim
#define NB 31            // blocks per dim
#define ORI 6
#define BLK_FEAT 24      // 2*2*ORI
#define HWsz (H*W)
#define NJOBS (B * NC * 2)   // 2048 half-strip jobs
#define GRID_A 1184          // 148 SMs * 8 CTAs/SM target
#define SMW 258              // 256 compute cols + 1 halo col each side

// scratch: per-cell histograms, (B, 32, 32, 6)
__device__ float g_cells[B * NC * NC * ORI];

// single-instruction MUFU.SQRT (sqrt.approx.f32: 0 -> 0, ~1ulp on normals)
__device__ __forceinline__ float fast_sqrt(float v) {
    float r;
    asm("sqrt.approx.f32 %0, %1;" : "=f"(r) : "f"(v));
    return r;
}

// ---------------------------------------------------------------------------
// Phase 2: gradients + suffix-histogram accumulation. S_k = sum of mag where
// bin >= k; the [bin>=k] predicates ARE the 5 sector boundary cross-product
// tests (bit-identical float expressions to the original 5-test binning).
// ---------------------------------------------------------------------------
template <bool BORDER>
__device__ __forceinline__ void phase2(
    const float (*sm)[SMW], int lcc, bool cok, int strip,
    float& S0, float& S1, float& S2, float& S3, float& S4, float& S5)
{
    const float C30 = 0.8660254037844386f;  // cos 30

    float w0 = sm[0][lcc];
    float w1 = sm[1][lcc];

    #pragma unroll
    for (int i = 0; i < 16; i++) {
        const float w2 = sm[i + 2][lcc];
        float gr = w2 - w0;
        if (BORDER) {
            const int r = strip * CELL + i;
            if (r == 0 || r == H - 1) gr = 0.0f;
        }
        const float gc = cok ? sm[i + 1][lcc + 1] - sm[i + 1][lcc - 1] : 0.0f;
        w0 = w1; w1 = w2;

        const float mag = fast_sqrt(gr * gr + gc * gc);

        // canonicalize to upper half-plane (angle mod 180 invariant)
        float X = gc, Y = gr;
        if (Y < 0.0f || (Y == 0.0f && X < 0.0f)) { X = -X; Y = -Y; }

        const float a  = C30 * Y;
        const float b2 = 0.5f * X;
        const float cc = 0.5f * Y;
        const float d  = C30 * X;

        S0 += mag;                                   // always
        S1 += ( a - b2  >= 0.0f) ? mag : 0.0f;       // angle >= 30
        S2 += ( cc - d  >= 0.0f) ? mag : 0.0f;       // angle >= 60
        S3 += (-X       >= 0.0f) ? mag : 0.0f;       // angle >= 90
        S4 += (-cc - d  >= 0.0f) ? mag : 0.0f;       // angle >= 120
        S5 += (-a - b2  >= 0.0f) ? mag : 0.0f;       // angle >= 150
    }
}

// ---------------------------------------------------------------------------
// Kernel A: persistent 256-thread CTAs over 2048 half-strip jobs.
// smem: 18 rows x 258 cols gray (1-col halo each side). ~18.1 KB/CTA ->
// up to 8 CTAs/SM: many independent load/compute streams per SM so DRAM
// stays busy while other CTAs are in their compute phase.
// ---------------------------------------------------------------------------
__global__ __launch_bounds__(256) void hog_cells_kernel(
    const float* __restrict__ x, float* __restrict__ cells)
{
    __shared__ float sm[18][SMW];
    const int c = threadIdx.x;          // 0..255
    const int lcc = c + 1;              // this thread's compute column in smem
    const bool ex = (c >= 254);         // threads 254,255 also load cols 256,257

    for (int job = blockIdx.x; job < NJOBS; job += GRID_A) {
        const int half  = job & 1;
        const int strip = (job >> 1) & (NC - 1);
        const int b     = job >> 6;

        const int base = half << 8;          // global col of compute col 0
        const float* xb = x + (size_t)b * 3 * HWsz;
        const int r0 = strip * CELL - 1;
        const bool border = (strip == 0) | (strip == NC - 1);

        // per-thread column validity (loop-invariant)
        const int g1 = base - 1 + c;        // main load col
        const bool v1 = (g1 >= 0) && (g1 < W);
        const int g2 = base + 1 + c;        // extra load col (c>=254 only)
        const bool v2 = ex && (g2 < W);

        const bool cok = (base + c > 0) && (base + c < W - 1);

        __syncthreads();   // protect smem from previous job's readers

        if (!border) {
            #pragma unroll
            for (int i = 0; i < 18; i++) {
                const float* row = xb + (r0 + i) * W;
                float g = 0.0f;
                if (v1) g = 0.299f * __ldg(row + g1)
                          + 0.587f * __ldg(row + HWsz + g1)
                          + 0.114f * __ldg(row + 2 * HWsz + g1);
                sm[i][c] = g;
                if (ex) {
                    float ge = 0.0f;
                    if (v2) ge = 0.299f * __ldg(row + g2)
                               + 0.587f * __ldg(row + HWsz + g2)
                               + 0.114f * __ldg(row + 2 * HWsz + g2);
                    sm[i][c + 2] = ge;
                }
            }
        } else {
            #pragma unroll
            for (int i = 0; i < 18; i++) {
                const int r = r0 + i;
                const bool rok = (r >= 0) && (r < H);
                const float* row = xb + r * W;
                float g = 0.0f;
                if (rok && v1) g = 0.299f * __ldg(row + g1)
                                 + 0.587f * __ldg(row + HWsz + g1)
                                 + 0.114f * __ldg(row + 2 * HWsz + g1);
                sm[i][c] = g;
                if (ex) {
                    float ge = 0.0f;
                    if (rok && v2) ge = 0.299f * __ldg(row + g2)
                                      + 0.587f * __ldg(row + HWsz + g2)
                                      + 0.114f * __ldg(row + 2 * HWsz + g2);
                    sm[i][c + 2] = ge;
                }
            }
        }
        __syncthreads();

        float S0 = 0.f, S1 = 0.f, S2 = 0.f, S3 = 0.f, S4 = 0.f, S5 = 0.f;

        if (!border) phase2<false>(sm, lcc, cok, strip, S0, S1, S2, S3, S4, S5);
        else         phase2<true >(sm, lcc, cok, strip, S0, S1, S2, S3, S4, S5);

        // reduce suffix sums across the 16 lanes of each column group
        #pragma unroll
        for (int s = 8; s; s >>= 1) {
            S0 += __shfl_xor_sync(0xffffffffu, S0, s);
            S1 += __shfl_xor_sync(0xffffffffu, S1, s);
            S2 += __shfl_xor_sync(0xffffffffu, S2, s);
            S3 += __shfl_xor_sync(0xffffffffu, S3, s);
            S4 += __shfl_xor_sync(0xffffffffu, S4, s);
            S5 += __shfl_xor_sync(0xffffffffu, S5, s);
        }

        if ((c & 15) == 0) {
            const int cellx = (base >> 4) + (c >> 4);
            float* dst = cells + (((size_t)b * NC + strip) * NC + cellx) * ORI;
            const float inv = 1.0f / (CELL * CELL);
            dst[0] = (S0 - S1) * inv;
            dst[1] = (S1 - S2) * inv;
            dst[2] = (S2 - S3) * inv;
            dst[3] = (S3 - S4) * inv;
            dst[4] = (S4 - S5) * inv;
            dst[5] = S5 * inv;
        }
    }

#if __CUDA_ARCH__ >= 900
    cudaTriggerProgrammaticLaunchCompletion();
#endif
}

// ---------------------------------------------------------------------------
// Kernel B: 8 lanes per HOG block; rsqrt-based L2-Hys. PDL-launched so its
// ramp overlaps kernel A's tail.
// ---------------------------------------------------------------------------
__global__ __launch_bounds__(256) void hog_blocks_kernel(
    const float* __restrict__ cells, float* __restrict__ out)
{
#if __CUDA_ARCH__ >= 900
    cudaGridDependencySynchronize();
#endif

    const int t = blockIdx.x * blockDim.x + threadIdx.x;
    const int g = t >> 3;           // HOG block index
    const int l = t & 7;            // lane within group
    const int total = B * NB * NB;
    if (g >= total) return;

    const int b  = g / (NB * NB);
    const int ij = g - b * (NB * NB);
    const int i  = ij / NB;
    const int j  = ij - i * NB;

    const int row = i + (l >> 2);
    const int off = (l & 3) * 3;
    const float* p = cells + (((size_t)b * NC + row) * NC + j) * ORI + off;

    float v0 = __ldg(p);
    float v1 = __ldg(p + 1);
    float v2 = __ldg(p + 2);

    const float EPS2 = 1e-10f;  // (1e-5)^2

    float ss = v0 * v0 + v1 * v1 + v2 * v2;
    #pragma unroll
    for (int s = 4; s; s >>= 1) ss += __shfl_xor_sync(0xffffffffu, ss, s);
    const float inv_n1 = rsqrtf(ss + EPS2);
    v0 = fminf(v0 * inv_n1, 0.2f);
    v1 = fminf(v1 * inv_n1, 0.2f);
    v2 = fminf(v2 * inv_n1, 0.2f);

    float ss2 = v0 * v0 + v1 * v1 + v2 * v2;
    #pragma unroll
    for (int s = 4; s; s >>= 1) ss2 += __shfl_xor_sync(0xffffffffu, ss2, s);
    const float inv_n2 = rsqrtf(ss2 + EPS2);

    float* o = out + (size_t)g * BLK_FEAT + l * 3;
    o[0] = v0 * inv_n2;
    o[1] = v1 * inv_n2;
    o[2] = v2 * inv_n2;
}

// ---------------------------------------------------------------------------
extern "C" void kernel_launch(void* const* d_in, const int* in_sizes, int n_in,
                              void* d_out, int out_size)
{
    const float* x = (const float*)d_in[0];
    float* out = (float*)d_out;

    float* cells;
    cudaGetSymbolAddress((void**)&cells, g_cells);

    hog_cells_kernel<<<GRID_A, 256>>>(x, cells);

    const int total = B * NB * NB;                 // 30752
    const int threadsB = total * 8;

    cudaLaunchConfig_t cfg = {};
    cfg.gridDim  = dim3((threadsB + 255) / 256);
    cfg.blockDim = dim3(256);
    cfg.dynamicSmemBytes = 0;
    cfg.stream = 0;
    cudaLaunchAttribute attrs[1];
    attrs[0].id = cudaLaunchAttributeProgrammaticStreamSerialization;
    attrs[0].val.programmaticStreamSerializationAllowed = 1;
    cfg.attrs = attrs;
    cfg.numAttrs = 1;
    cudaLaunchKernelEx(&cfg, hog_blocks_kernel, (const float*)cells, out);
}

// round 11
// speedup vs baseline: 1.1046x; 1.1046x over previous
#include <cuda_runtime.h>
#include <cuda_bf16.h>
#include <math.h>

#define H 512
#define W 512
#define B 32
#define CELL 16
#define NC 32            // cells per dim
#define NB 31            // blocks per dim
#define ORI 6
#define BLK_FEAT 24      // 2*2*ORI
#define HWsz (H*W)
#define NJOBS (B * NC * 16)  // 16384 warp-jobs: (image, strip, 32-col block)

// scratch: per-cell histograms, (B, 32, 32, 6)
__device__ float g_cells[B * NC * NC * ORI];

// single-instruction MUFU.SQRT (sqrt.approx.f32: 0 -> 0, ~1ulp on normals)
__device__ __forceinline__ float fast_sqrt(float v) {
    float r;
    asm("sqrt.approx.f32 %0, %1;" : "=f"(r) : "f"(v));
    return r;
}

__device__ __forceinline__ float gray_at(const float* xb, int r, int c) {
    const int p = r * W + c;
    return 0.299f * __ldg(xb + p)
         + 0.587f * __ldg(xb + HWsz + p)
         + 0.114f * __ldg(xb + 2 * HWsz + p);
}

// ---------------------------------------------------------------------------
// Kernel A: one WARP per (image, cell-row strip, 32-column block).
// No shared memory, no barriers: each lane holds its column's 18-row gray
// window in registers; vertical gradient from own registers, horizontal
// gradient via shfl from lanes +-1 (edge lanes fetch the outside column with
// predicated loads). Warps are fully independent -> loads of some warps
// overlap compute of others with no phase convoy.
// ---------------------------------------------------------------------------
template <bool BORDER>
__device__ __forceinline__ void warp_job(
    const float* __restrict__ xb, int strip, int bimg, int colblk,
    float* __restrict__ cells)
{
    const int lane = threadIdx.x & 31;
    const int c = (colblk << 5) + lane;     // this lane's column
    const int r0 = strip * CELL - 1;

    // ---- own-column gray window: 18 rows (halo of 1 each side) ----
    float win[18];
    if (!BORDER) {
        #pragma unroll
        for (int lr = 0; lr < 18; lr++)
            win[lr] = gray_at(xb, r0 + lr, c);
    } else {
        #pragma unroll
        for (int lr = 0; lr < 18; lr++) {
            const int r = r0 + lr;
            win[lr] = (r >= 0 && r < H) ? gray_at(xb, r, c) : 0.0f;
        }
    }

    // ---- edge-neighbor column (outside the warp) for lanes 0 / 31 ----
    // rows needed are the 16 output rows strip*16+i, always in [0, H).
    float ev[16];
    const int cE = (lane == 0) ? c - 1 : c + 1;
    const bool pLoad = ((lane == 0) & (c > 0)) | ((lane == 31) & (c < W - 1));
    if (pLoad) {
        #pragma unroll
        for (int i = 0; i < 16; i++)
            ev[i] = gray_at(xb, strip * CELL + i, cE);
    } else {
        #pragma unroll
        for (int i = 0; i < 16; i++) ev[i] = 0.0f;
    }

    const bool cok = (c > 0) && (c < W - 1);
    const float C30 = 0.8660254037844386f;  // cos 30

    float S0 = 0.f, S1 = 0.f, S2 = 0.f, S3 = 0.f, S4 = 0.f, S5 = 0.f;

    #pragma unroll
    for (int i = 0; i < 16; i++) {
        float gr = win[i + 2] - win[i];
        if (BORDER) {
            const int r = strip * CELL + i;
            if (r == 0 || r == H - 1) gr = 0.0f;
        }

        // horizontal neighbors of row i+1 live in lanes +-1's win[i+1]
        const float mid = win[i + 1];
        float left  = __shfl_up_sync(0xffffffffu, mid, 1);
        float right = __shfl_down_sync(0xffffffffu, mid, 1);
        if (lane == 0)  left  = ev[i];
        if (lane == 31) right = ev[i];
        const float gc = cok ? right - left : 0.0f;

        const float mag = fast_sqrt(gr * gr + gc * gc);

        // canonicalize to upper half-plane (angle mod 180 invariant)
        float X = gc, Y = gr;
        if (Y < 0.0f || (Y == 0.0f && X < 0.0f)) { X = -X; Y = -Y; }

        const float a  = C30 * Y;
        const float b2 = 0.5f * X;
        const float cc = 0.5f * Y;
        const float d  = C30 * X;

        // suffix histogram: S_k = sum of mag where angle >= 30k
        S0 += mag;
        S1 += ( a - b2  >= 0.0f) ? mag : 0.0f;   // >= 30
        S2 += ( cc - d  >= 0.0f) ? mag : 0.0f;   // >= 60
        S3 += (-X       >= 0.0f) ? mag : 0.0f;   // >= 90
        S4 += (-cc - d  >= 0.0f) ? mag : 0.0f;   // >= 120
        S5 += (-a - b2  >= 0.0f) ? mag : 0.0f;   // >= 150
    }

    // reduce across the 16 lanes of each cell group
    #pragma unroll
    for (int s = 8; s; s >>= 1) {
        S0 += __shfl_xor_sync(0xffffffffu, S0, s);
        S1 += __shfl_xor_sync(0xffffffffu, S1, s);
        S2 += __shfl_xor_sync(0xffffffffu, S2, s);
        S3 += __shfl_xor_sync(0xffffffffu, S3, s);
        S4 += __shfl_xor_sync(0xffffffffu, S4, s);
        S5 += __shfl_xor_sync(0xffffffffu, S5, s);
    }

    if ((lane & 15) == 0) {
        const int cellx = c >> 4;
        float* dst = cells + (((size_t)bimg * NC + strip) * NC + cellx) * ORI;
        const float inv = 1.0f / (CELL * CELL);
        dst[0] = (S0 - S1) * inv;
        dst[1] = (S1 - S2) * inv;
        dst[2] = (S2 - S3) * inv;
        dst[3] = (S3 - S4) * inv;
        dst[4] = (S4 - S5) * inv;
        dst[5] = S5 * inv;
    }
}

__global__ __launch_bounds__(256) void hog_cells_kernel(
    const float* __restrict__ x, float* __restrict__ cells)
{
    const int wid = blockIdx.x * 8 + (threadIdx.x >> 5);   // global warp id
    if (wid >= NJOBS) return;

    const int colblk = wid & 15;
    const int strip  = (wid >> 4) & (NC - 1);
    const int bimg   = wid >> 9;

    const float* xb = x + (size_t)bimg * 3 * HWsz;

    if (strip != 0 && strip != NC - 1)
        warp_job<false>(xb, strip, bimg, colblk, cells);
    else
        warp_job<true >(xb, strip, bimg, colblk, cells);

#if __CUDA_ARCH__ >= 900
    cudaTriggerProgrammaticLaunchCompletion();
#endif
}

// ---------------------------------------------------------------------------
// Kernel B: 8 lanes per HOG block; rsqrt-based L2-Hys. PDL-launched so its
// ramp overlaps kernel A's tail.
// ---------------------------------------------------------------------------
__global__ __launch_bounds__(256) void hog_blocks_kernel(
    const float* __restrict__ cells, float* __restrict__ out)
{
#if __CUDA_ARCH__ >= 900
    cudaGridDependencySynchronize();
#endif

    const int t = blockIdx.x * blockDim.x + threadIdx.x;
    const int g = t >> 3;           // HOG block index
    const int l = t & 7;            // lane within group
    const int total = B * NB * NB;
    if (g >= total) return;

    const int b  = g / (NB * NB);
    const int ij = g - b * (NB * NB);
    const int i  = ij / NB;
    const int j  = ij - i * NB;

    const int row = i + (l >> 2);
    const int off = (l & 3) * 3;
    const float* p = cells + (((size_t)b * NC + row) * NC + j) * ORI + off;

    float v0 = __ldg(p);
    float v1 = __ldg(p + 1);
    float v2 = __ldg(p + 2);

    const float EPS2 = 1e-10f;  // (1e-5)^2

    float ss = v0 * v0 + v1 * v1 + v2 * v2;
    #pragma unroll
    for (int s = 4; s; s >>= 1) ss += __shfl_xor_sync(0xffffffffu, ss, s);
    const float inv_n1 = rsqrtf(ss + EPS2);
    v0 = fminf(v0 * inv_n1, 0.2f);
    v1 = fminf(v1 * inv_n1, 0.2f);
    v2 = fminf(v2 * inv_n1, 0.2f);

    float ss2 = v0 * v0 + v1 * v1 + v2 * v2;
    #pragma unroll
    for (int s = 4; s; s >>= 1) ss2 += __shfl_xor_sync(0xffffffffu, ss2, s);
    const float inv_n2 = rsqrtf(ss2 + EPS2);

    float* o = out + (size_t)g * BLK_FEAT + l * 3;
    o[0] = v0 * inv_n2;
    o[1] = v1 * inv_n2;
    o[2] = v2 * inv_n2;
}

// ---------------------------------------------------------------------------
extern "C" void kernel_launch(void* const* d_in, const int* in_sizes, int n_in,
                              void* d_out, int out_size)
{
    const float* x = (const float*)d_in[0];
    float* out = (float*)d_out;

    float* cells;
    cudaGetSymbolAddress((void**)&cells, g_cells);

    hog_cells_kernel<<<NJOBS / 8, 256>>>(x, cells);   // 2048 CTAs x 8 warps

    const int total = B * NB * NB;                 // 30752
    const int threadsB = total * 8;

    cudaLaunchConfig_t cfg = {};
    cfg.gridDim  = dim3((threadsB + 255) / 256);
    cfg.blockDim = dim3(256);
    cfg.dynamicSmemBytes = 0;
    cfg.stream = 0;
    cudaLaunchAttribute attrs[1];
    attrs[0].id = cudaLaunchAttributeProgrammaticStreamSerialization;
    attrs[0].val.programmaticStreamSerializationAllowed = 1;
    cfg.attrs = attrs;
    cfg.numAttrs = 1;
    cudaLaunchKernelEx(&cfg, hog_blocks_kernel, (const float*)cells, out);
}

// round 12
// speedup vs baseline: 1.1822x; 1.0703x over previous
#include <cuda_runtime.h>
#include <cuda_bf16.h>
#include <math.h>

#define H 512
#define W 512
#define B 32
#define CELL 16
#define NC 32            // cells per dim
#define NB 31            // blocks per dim
#define ORI 6
#define BLK_FEAT 24      // 2*2*ORI
#define HWsz (H*W)
#define NJOBS (B * NC * 16)  // 16384 warp-jobs: (image, strip, 32-col block)

// scratch: per-cell histograms, (B, 32, 32, 6)
__device__ float g_cells[B * NC * NC * ORI];

// single-instruction MUFU.SQRT (sqrt.approx.f32: 0 -> 0, ~1ulp on normals)
__device__ __forceinline__ float fast_sqrt(float v) {
    float r;
    asm("sqrt.approx.f32 %0, %1;" : "=f"(r) : "f"(v));
    return r;
}

__device__ __forceinline__ float gray_at(const float* xb, int r, int c) {
    const int p = r * W + c;
    return 0.299f * __ldg(xb + p)
         + 0.587f * __ldg(xb + HWsz + p)
         + 0.114f * __ldg(xb + 2 * HWsz + p);
}

// ---------------------------------------------------------------------------
// Kernel A: one WARP per (image, cell-row strip, 32-column block).
// Barrier-free and smem-free. Each lane holds its column's 18-row gray
// window in registers. Halo columns are loaded COOPERATIVELY: lanes 0-15
// hold the left halo column's 16 rows (one row per lane), lanes 16-31 the
// right halo column; per-row values reach lanes 0/31 via one shfl each.
// ---------------------------------------------------------------------------
template <bool BORDER>
__device__ __forceinline__ void warp_job(
    const float* __restrict__ xb, int strip, int bimg, int colblk,
    float* __restrict__ cells)
{
    const int lane = threadIdx.x & 31;
    const int base = colblk << 5;
    const int c = base + lane;              // this lane's column
    const int r0 = strip * CELL - 1;

    // ---- own-column gray window: 18 rows (halo of 1 each side) ----
    float win[18];
    if (!BORDER) {
        #pragma unroll
        for (int lr = 0; lr < 18; lr++)
            win[lr] = gray_at(xb, r0 + lr, c);
    } else {
        #pragma unroll
        for (int lr = 0; lr < 18; lr++) {
            const int r = r0 + lr;
            win[lr] = (r >= 0 && r < H) ? gray_at(xb, r, c) : 0.0f;
        }
    }

    // ---- cooperative halo-column load: one row per lane ----
    // lanes 0..15:  left col (base-1),  row strip*16 + lane
    // lanes 16..31: right col (base+32), row strip*16 + lane-16
    // Invalid cols (off-image) are clamped; values unused (cok masks them).
    {
    }
    const int hrow = strip * CELL + (lane & 15);
    int hcol = (lane < 16) ? base - 1 : base + 32;
    hcol = max(0, min(W - 1, hcol));
    const float evv = gray_at(xb, hrow, hcol);

    const bool cok = (c > 0) && (c < W - 1);
    const float C30 = 0.8660254037844386f;  // cos 30

    float S0 = 0.f, S1 = 0.f, S2 = 0.f, S3 = 0.f, S4 = 0.f, S5 = 0.f;

    #pragma unroll
    for (int i = 0; i < 16; i++) {
        float gr = win[i + 2] - win[i];
        if (BORDER) {
            const int r = strip * CELL + i;
            if (r == 0 || r == H - 1) gr = 0.0f;
        }

        // horizontal neighbors of row i+1: lanes +-1's win[i+1], except at
        // warp edges where the cooperative halo registers supply them.
        const float mid = win[i + 1];
        const float lv = __shfl_sync(0xffffffffu, evv, i);        // left halo row i
        const float rv = __shfl_sync(0xffffffffu, evv, 16 + i);   // right halo row i
        float left  = __shfl_up_sync(0xffffffffu, mid, 1);
        float right = __shfl_down_sync(0xffffffffu, mid, 1);
        if (lane == 0)  left  = lv;
        if (lane == 31) right = rv;
        const float gc = cok ? right - left : 0.0f;

        const float mag = fast_sqrt(gr * gr + gc * gc);

        // canonicalize to upper half-plane (angle mod 180 invariant)
        float X = gc, Y = gr;
        if (Y < 0.0f || (Y == 0.0f && X < 0.0f)) { X = -X; Y = -Y; }

        const float a  = C30 * Y;
        const float b2 = 0.5f * X;
        const float cc = 0.5f * Y;
        const float d  = C30 * X;

        // suffix histogram: S_k = sum of mag where angle >= 30k
        S0 += mag;
        S1 += ( a - b2  >= 0.0f) ? mag : 0.0f;   // >= 30
        S2 += ( cc - d  >= 0.0f) ? mag : 0.0f;   // >= 60
        S3 += (-X       >= 0.0f) ? mag : 0.0f;   // >= 90
        S4 += (-cc - d  >= 0.0f) ? mag : 0.0f;   // >= 120
        S5 += (-a - b2  >= 0.0f) ? mag : 0.0f;   // >= 150
    }

    // reduce across the 16 lanes of each cell group
    #pragma unroll
    for (int s = 8; s; s >>= 1) {
        S0 += __shfl_xor_sync(0xffffffffu, S0, s);
        S1 += __shfl_xor_sync(0xffffffffu, S1, s);
        S2 += __shfl_xor_sync(0xffffffffu, S2, s);
        S3 += __shfl_xor_sync(0xffffffffu, S3, s);
        S4 += __shfl_xor_sync(0xffffffffu, S4, s);
        S5 += __shfl_xor_sync(0xffffffffu, S5, s);
    }

    if ((lane & 15) == 0) {
        const int cellx = c >> 4;
        float* dst = cells + (((size_t)bimg * NC + strip) * NC + cellx) * ORI;
        const float inv = 1.0f / (CELL * CELL);
        dst[0] = (S0 - S1) * inv;
        dst[1] = (S1 - S2) * inv;
        dst[2] = (S2 - S3) * inv;
        dst[3] = (S3 - S4) * inv;
        dst[4] = (S4 - S5) * inv;
        dst[5] = S5 * inv;
    }
}

__global__ __launch_bounds__(256) void hog_cells_kernel(
    const float* __restrict__ x, float* __restrict__ cells)
{
    const int wid = blockIdx.x * 8 + (threadIdx.x >> 5);   // global warp id
    if (wid < NJOBS) {
        const int colblk = wid & 15;
        const int strip  = (wid >> 4) & (NC - 1);
        const int bimg   = wid >> 9;

        const float* xb = x + (size_t)bimg * 3 * HWsz;

        if (strip != 0 && strip != NC - 1)
            warp_job<false>(xb, strip, bimg, colblk, cells);
        else
            warp_job<true >(xb, strip, bimg, colblk, cells);
    }

#if __CUDA_ARCH__ >= 900
    cudaTriggerProgrammaticLaunchCompletion();
#endif
}

// ---------------------------------------------------------------------------
// Kernel B: 8 lanes per HOG block; rsqrt-based L2-Hys. PDL-launched so its
// ramp overlaps kernel A's tail.
// ---------------------------------------------------------------------------
__global__ __launch_bounds__(256) void hog_blocks_kernel(
    const float* __restrict__ cells, float* __restrict__ out)
{
#if __CUDA_ARCH__ >= 900
    cudaGridDependencySynchronize();
#endif

    const int t = blockIdx.x * blockDim.x + threadIdx.x;
    const int g = t >> 3;           // HOG block index
    const int l = t & 7;            // lane within group
    const int total = B * NB * NB;
    if (g >= total) return;

    const int b  = g / (NB * NB);
    const int ij = g - b * (NB * NB);
    const int i  = ij / NB;
    const int j  = ij - i * NB;

    const int row = i + (l >> 2);
    const int off = (l & 3) * 3;
    const float* p = cells + (((size_t)b * NC + row) * NC + j) * ORI + off;

    float v0 = __ldg(p);
    float v1 = __ldg(p + 1);
    float v2 = __ldg(p + 2);

    const float EPS2 = 1e-10f;  // (1e-5)^2

    float ss = v0 * v0 + v1 * v1 + v2 * v2;
    #pragma unroll
    for (int s = 4; s; s >>= 1) ss += __shfl_xor_sync(0xffffffffu, ss, s);
    const float inv_n1 = rsqrtf(ss + EPS2);
    v0 = fminf(v0 * inv_n1, 0.2f);
    v1 = fminf(v1 * inv_n1, 0.2f);
    v2 = fminf(v2 * inv_n1, 0.2f);

    float ss2 = v0 * v0 + v1 * v1 + v2 * v2;
    #pragma unroll
    for (int s = 4; s; s >>= 1) ss2 += __shfl_xor_sync(0xffffffffu, ss2, s);
    const float inv_n2 = rsqrtf(ss2 + EPS2);

    float* o = out + (size_t)g * BLK_FEAT + l * 3;
    o[0] = v0 * inv_n2;
    o[1] = v1 * inv_n2;
    o[2] = v2 * inv_n2;
}

// ---------------------------------------------------------------------------
extern "C" void kernel_launch(void* const* d_in, const int* in_sizes, int n_in,
                              void* d_out, int out_size)
{
    const float* x = (const float*)d_in[0];
    float* out = (float*)d_out;

    float* cells;
    cudaGetSymbolAddress((void**)&cells, g_cells);

    hog_cells_kernel<<<NJOBS / 8, 256>>>(x, cells);   // 2048 CTAs x 8 warps

    const int total = B * NB * NB;                 // 30752
    const int threadsB = total * 8;

    cudaLaunchConfig_t cfg = {};
    cfg.gridDim  = dim3((threadsB + 255) / 256);
    cfg.blockDim = dim3(256);
    cfg.dynamicSmemBytes = 0;
    cfg.stream = 0;
    cudaLaunchAttribute attrs[1];
    attrs[0].id = cudaLaunchAttributeProgrammaticStreamSerialization;
    attrs[0].val.programmaticStreamSerializationAllowed = 1;
    cfg.attrs = attrs;
    cfg.numAttrs = 1;
    cudaLaunchKernelEx(&cfg, hog_blocks_kernel, (const float*)cells, out);
}

// round 13
// speedup vs baseline: 1.3616x; 1.1517x over previous
#include <cuda_runtime.h>
#include <cuda_bf16.h>
#include <math.h>

#define H 512
#define W 512
#define B 32
#define CELL 16
#define NC 32            // cells per dim
#define NB 31            // blocks per dim
#define ORI 6
#define BLK_FEAT 24      // 2*2*ORI
#define HWsz (H*W)
#define NSTRIPS (B * NC) // 1024 jobs
#define GRID_A 592       // 148 SMs * 4 CTAs/SM (512thr, 36KB smem)

// scratch: per-cell histograms, (B, 32, 32, 6)
__device__ float g_cells[B * NC * NC * ORI];

// single-instruction MUFU.SQRT (sqrt.approx.f32: 0 -> 0, ~1ulp on normals)
__device__ __forceinline__ float fast_sqrt(float v) {
    float r;
    asm("sqrt.approx.f32 %0, %1;" : "=f"(r) : "f"(v));
    return r;
}

// ---------------------------------------------------------------------------
// Phase 2: gradients + suffix-histogram accumulation. S_k = sum of mag where
// bin >= k. The [bin>=k] predicates are the 5 sector boundary tests, written
// as DIRECT FSETP comparisons: fl(u-v)>=0 <=> u>=v (IEEE RN, exact sign), so
// this is bit-identical to the difference-then-compare form but saves 4
// FADDs per pixel (negations fold into FSETP operand modifiers).
// ---------------------------------------------------------------------------
template <bool BORDER>
__device__ __forceinline__ void phase2(
    const float (*sm)[512], int c, bool cok, int strip,
    float& S0, float& S1, float& S2, float& S3, float& S4, float& S5)
{
    const float C30 = 0.8660254037844386f;  // cos 30

    // rolling register window over own column: gr = sm[i+2][c] - sm[i][c]
    float w0 = sm[0][c];
    float w1 = sm[1][c];

    #pragma unroll
    for (int i = 0; i < 16; i++) {
        const float w2 = sm[i + 2][c];
        float gr = w2 - w0;
        if (BORDER) {
            const int r = strip * CELL + i;
            if (r == 0 || r == H - 1) gr = 0.0f;
        }
        const float gc = cok ? sm[i + 1][c + 1] - sm[i + 1][c - 1] : 0.0f;
        w0 = w1; w1 = w2;

        const float mag = fast_sqrt(gr * gr + gc * gc);

        // canonicalize to upper half-plane (angle mod 180 invariant)
        float X = gc, Y = gr;
        if (Y < 0.0f || (Y == 0.0f && X < 0.0f)) { X = -X; Y = -Y; }

        const float a  = C30 * Y;
        const float b2 = 0.5f * X;
        const float cc = 0.5f * Y;
        const float d  = C30 * X;

        S0 += mag;                               // always
        S1 += ( a  >= b2  ) ? mag : 0.0f;        // angle >= 30
        S2 += ( cc >= d   ) ? mag : 0.0f;        // angle >= 60
        S3 += ( X  <= 0.0f) ? mag : 0.0f;        // angle >= 90
        S4 += (-cc >= d   ) ? mag : 0.0f;        // angle >= 120
        S5 += (-a  >= b2  ) ? mag : 0.0f;        // angle >= 150
    }
}

// ---------------------------------------------------------------------------
// Kernel A: persistent strip CTAs, float2-vectorized load phase.
// 18 rows x 256 float2-slots = 4608 = exactly 9 iterations of 512 threads.
// ---------------------------------------------------------------------------
__global__ __launch_bounds__(512) void hog_cells_kernel(
    const float* __restrict__ x, float* __restrict__ cells)
{
    __shared__ float sm[18][512];
    const int tid = threadIdx.x;
    const int c = tid;              // column for phase 2
    const bool cok = (c > 0) && (c < W - 1);

    const int lrow_half = tid >> 8;          // 0 or 1
    const int col2 = (tid & 255);            // float2 slot in row
    const int colb = col2 << 1;              // float column

    for (int job = blockIdx.x; job < NSTRIPS; job += GRID_A) {
        const int strip = job & (NC - 1);   // cell row 0..31
        const int b     = job >> 5;         // image

        const float* xb = x + (size_t)b * 3 * HWsz;
        const int r0 = strip * CELL - 1;
        const bool border = (strip == 0) | (strip == NC - 1);

        __syncthreads();   // protect smem from previous iteration's readers

        if (!border) {
            #pragma unroll
            for (int it = 0; it < 9; it++) {
                const int i = 2 * it + lrow_half;      // local row 0..17
                const float2* base = (const float2*)(xb + (r0 + i) * W) + col2;
                const float2 R  = __ldg(base);
                const float2 G  = __ldg(base + (HWsz >> 1));
                const float2 Bc = __ldg(base + HWsz);
                float2 g;
                g.x = 0.299f * R.x + 0.587f * G.x + 0.114f * Bc.x;
                g.y = 0.299f * R.y + 0.587f * G.y + 0.114f * Bc.y;
                *((float2*)&sm[i][colb]) = g;
            }
        } else {
            #pragma unroll
            for (int it = 0; it < 9; it++) {
                const int i = 2 * it + lrow_half;
                const int r = r0 + i;
                float2 g = make_float2(0.f, 0.f);
                if (r >= 0 && r < H) {
                    const float2* base = (const float2*)(xb + r * W) + col2;
                    const float2 R  = __ldg(base);
                    const float2 G  = __ldg(base + (HWsz >> 1));
                    const float2 Bc = __ldg(base + HWsz);
                    g.x = 0.299f * R.x + 0.587f * G.x + 0.114f * Bc.x;
                    g.y = 0.299f * R.y + 0.587f * G.y + 0.114f * Bc.y;
                }
                *((float2*)&sm[i][colb]) = g;
            }
        }
        __syncthreads();

        float S0 = 0.f, S1 = 0.f, S2 = 0.f, S3 = 0.f, S4 = 0.f, S5 = 0.f;

        if (!border) phase2<false>(sm, c, cok, strip, S0, S1, S2, S3, S4, S5);
        else         phase2<true >(sm, c, cok, strip, S0, S1, S2, S3, S4, S5);

        // reduce suffix sums across the 16 lanes of each column group
        #pragma unroll
        for (int s = 8; s; s >>= 1) {
            S0 += __shfl_xor_sync(0xffffffffu, S0, s);
            S1 += __shfl_xor_sync(0xffffffffu, S1, s);
            S2 += __shfl_xor_sync(0xffffffffu, S2, s);
            S3 += __shfl_xor_sync(0xffffffffu, S3, s);
            S4 += __shfl_xor_sync(0xffffffffu, S4, s);
            S5 += __shfl_xor_sync(0xffffffffu, S5, s);
        }

        if ((c & 15) == 0) {
            const int cellx = c >> 4;
            float* dst = cells + (((size_t)b * NC + strip) * NC + cellx) * ORI;
            const float inv = 1.0f / (CELL * CELL);
            dst[0] = (S0 - S1) * inv;
            dst[1] = (S1 - S2) * inv;
            dst[2] = (S2 - S3) * inv;
            dst[3] = (S3 - S4) * inv;
            dst[4] = (S4 - S5) * inv;
            dst[5] = S5 * inv;
        }
    }

#if __CUDA_ARCH__ >= 900
    cudaTriggerProgrammaticLaunchCompletion();
#endif
}

// ---------------------------------------------------------------------------
// Kernel B: 8 lanes per HOG block; rsqrt-based L2-Hys. PDL-launched so its
// ramp overlaps kernel A's tail.
// ---------------------------------------------------------------------------
__global__ __launch_bounds__(256) void hog_blocks_kernel(
    const float* __restrict__ cells, float* __restrict__ out)
{
#if __CUDA_ARCH__ >= 900
    cudaGridDependencySynchronize();
#endif

    const int t = blockIdx.x * blockDim.x + threadIdx.x;
    const int g = t >> 3;           // HOG block index
    const int l = t & 7;            // lane within group
    const int total = B * NB * NB;
    if (g >= total) return;

    const int b  = g / (NB * NB);
    const int ij = g - b * (NB * NB);
    const int i  = ij / NB;
    const int j  = ij - i * NB;

    const int row = i + (l >> 2);
    const int off = (l & 3) * 3;
    const float* p = cells + (((size_t)b * NC + row) * NC + j) * ORI + off;

    float v0 = __ldg(p);
    float v1 = __ldg(p + 1);
    float v2 = __ldg(p + 2);

    const float EPS2 = 1e-10f;  // (1e-5)^2

    float ss = v0 * v0 + v1 * v1 + v2 * v2;
    #pragma unroll
    for (int s = 4; s; s >>= 1) ss += __shfl_xor_sync(0xffffffffu, ss, s);
    const float inv_n1 = rsqrtf(ss + EPS2);
    v0 = fminf(v0 * inv_n1, 0.2f);
    v1 = fminf(v1 * inv_n1, 0.2f);
    v2 = fminf(v2 * inv_n1, 0.2f);

    float ss2 = v0 * v0 + v1 * v1 + v2 * v2;
    #pragma unroll
    for (int s = 4; s; s >>= 1) ss2 += __shfl_xor_sync(0xffffffffu, ss2, s);
    const float inv_n2 = rsqrtf(ss2 + EPS2);

    float* o = out + (size_t)g * BLK_FEAT + l * 3;
    o[0] = v0 * inv_n2;
    o[1] = v1 * inv_n2;
    o[2] = v2 * inv_n2;
}

// ---------------------------------------------------------------------------
extern "C" void kernel_launch(void* const* d_in, const int* in_sizes, int n_in,
                              void* d_out, int out_size)
{
    const float* x = (const float*)d_in[0];
    float* out = (float*)d_out;

    float* cells;
    cudaGetSymbolAddress((void**)&cells, g_cells);

    hog_cells_kernel<<<GRID_A, 512>>>(x, cells);

    const int total = B * NB * NB;                 // 30752
    const int threadsB = total * 8;

    cudaLaunchConfig_t cfg = {};
    cfg.gridDim  = dim3((threadsB + 255) / 256);
    cfg.blockDim = dim3(256);
    cfg.dynamicSmemBytes = 0;
    cfg.stream = 0;
    cudaLaunchAttribute attrs[1];
    attrs[0].id = cudaLaunchAttributeProgrammaticStreamSerialization;
    attrs[0].val.programmaticStreamSerializationAllowed = 1;
    cfg.attrs = attrs;
    cfg.numAttrs = 1;
    cudaLaunchKernelEx(&cfg, hog_blocks_kernel, (const float*)cells, out);
}